// round 9
// baseline (speedup 1.0000x reference)
#include <cuda_runtime.h>
#include <math.h>

#define D 128
#define H 4
#define NMAX 500000
#define BMAX 8192
#define FAST_CAP 128    // fast-path max segment length (mean 61, sigma 7.8)
#define NT 256          // 8 warps; 2 segments x 4 warps
#define WPS 4           // warps per segment
#define KREG 8          // register rows per warp -> covers n < 32 per segment

// Global scratch (fallback path only) + segment starts.
__device__ float4 g_scores[NMAX];
__device__ int    g_seg_start[BMAX + 1];

// ---------------------------------------------------------------------------
// Dtype-agnostic ids (reference claims int64 but JAX x64-off gives int32).
// ---------------------------------------------------------------------------
__device__ __forceinline__ bool ids_are_64bit(const int* ids32, int N) {
    int j = ((N - 1) & 1) ? (N - 1) : (N - 2);
    if (j < 0) j = 0;
    return ids32[j] == 0;
}
__device__ __forceinline__ int get_id_raw(const void* ids, bool is64, int n) {
    return is64 ? (int)((const long long*)ids)[n] : ((const int*)ids)[n];
}

__global__ void k_bounds(const void* __restrict__ ids, int N, int B) {
    int b = blockIdx.x * blockDim.x + threadIdx.x;
    if (b > B) return;
    bool is64 = ids_are_64bit((const int*)ids, N);
    int lo = 0, hi = N;
    while (lo < hi) {
        int mid = (lo + hi) >> 1;
        if (get_id_raw(ids, is64, mid) < b) lo = mid + 1; else hi = mid;
    }
    g_seg_start[b] = lo;
}

// ---------------------------------------------------------------------------
// 4-head warp reduction in 6 shuffles. Lane l ends with the full 32-lane sum
// of head (l & 3), replicated across each 4-lane group.
// ---------------------------------------------------------------------------
__device__ __forceinline__ float reduce4_heads(float s0, float s1, float s2,
                                               float s3, int lane) {
    const unsigned FULL = 0xFFFFFFFFu;
    float a01_send = (lane & 1) ? s0 : s1;
    float a01 = ((lane & 1) ? s1 : s0) + __shfl_xor_sync(FULL, a01_send, 1);
    float a23_send = (lane & 1) ? s2 : s3;
    float a23 = ((lane & 1) ? s3 : s2) + __shfl_xor_sync(FULL, a23_send, 1);
    float b_send = (lane & 2) ? a01 : a23;
    float v = ((lane & 2) ? a23 : a01) + __shfl_xor_sync(FULL, b_send, 2);
    v += __shfl_xor_sync(FULL, v, 4);
    v += __shfl_xor_sync(FULL, v, 8);
    v += __shfl_xor_sync(FULL, v, 16);
    return v;
}

// Segment-scoped barrier: ids 1 and 2, 128 threads each.
__device__ __forceinline__ void seg_bar(int seg) {
    asm volatile("bar.sync %0, %1;" :: "r"(seg + 1), "r"(128) : "memory");
}

// ---------------------------------------------------------------------------
// Fused kernel: TWO segments per block. Warps 0-3 -> segment A (tids 0-127),
// warps 4-7 -> segment B (tids 128-255). All sync via per-segment named
// barriers; zero full-block barriers -> the two segments' phases overlap.
// Per-segment smem (floats): sc[512] | w_s[128] | pool4[4*32*4] | wred[4*4]
//   = 1168 floats; x2 segments = 9344 bytes.
// ---------------------------------------------------------------------------
__global__ void __launch_bounds__(NT, 3) k_fused(
    const float* __restrict__ x,
    const float* __restrict__ W,
    const float* __restrict__ bias,
    const float* __restrict__ temp,
    float* __restrict__ out_pooled,   // [B, D]
    float* __restrict__ out_attn,     // [H, N]
    int N, int B)
{
    extern __shared__ float sdyn[];

    int tid  = threadIdx.x;
    int seg  = tid >> 7;          // 0 or 1
    int st   = tid & 127;         // segment-local tid
    int lane = tid & 31;
    int wl   = (tid >> 5) & 3;    // warp index within segment (0-3)

    float* base  = sdyn + seg * 1168;
    float*  sc_f  = base;
    float4* sc_s  = (float4*)base;
    float*  w_s   = base + 512;
    float4* pool4 = (float4*)(base + 640);
    float4* wred  = (float4*)(base + 1152);

    int b = blockIdx.x * 2 + seg;
    if (b >= B) return;

    int start = g_seg_start[b];
    int end   = g_seg_start[b + 1];
    int len   = end - start;

    float4 w0 = ((const float4*)W)[lane];
    float4 w1 = ((const float4*)W)[32 + lane];
    float4 w2 = ((const float4*)W)[64 + lane];
    float4 w3 = ((const float4*)W)[96 + lane];
    float  b_l  = bias[lane & 3];
    float  tinv = 1.0f / temp[0];

    const float4* xg4 = (const float4*)(x + (size_t)start * D);

    if (len <= FAST_CAP) {
        // ---- prefetch KREG rows per warp (MLP=8); covers n < 32 ----
        float4 xr[KREG];
        #pragma unroll
        for (int k = 0; k < KREG; k++) {
            int n = wl + k * WPS;
            if (n < len) xr[k] = xg4[n * 32 + lane];
        }

        // ---- scores from registers (6-shuffle head reduction) ----
        #pragma unroll
        for (int k = 0; k < KREG; k++) {
            int n = wl + k * WPS;
            if (n < len) {
                float4 xv = xr[k];
                float s0 = xv.x * w0.x + xv.y * w0.y + xv.z * w0.z + xv.w * w0.w;
                float s1 = xv.x * w1.x + xv.y * w1.y + xv.z * w1.z + xv.w * w1.w;
                float s2 = xv.x * w2.x + xv.y * w2.y + xv.z * w2.z + xv.w * w2.w;
                float s3 = xv.x * w3.x + xv.y * w3.y + xv.z * w3.z + xv.w * w3.w;
                float v = reduce4_heads(s0, s1, s2, s3, lane);
                if (lane < 4) sc_f[n * 4 + lane] = (v + b_l) * tinv;
            }
        }
        // ---- tail rows (n >= 32) ----
        for (int n = wl + KREG * WPS; n < len; n += WPS) {
            float4 xv = xg4[n * 32 + lane];
            float s0 = xv.x * w0.x + xv.y * w0.y + xv.z * w0.z + xv.w * w0.w;
            float s1 = xv.x * w1.x + xv.y * w1.y + xv.z * w1.z + xv.w * w1.w;
            float s2 = xv.x * w2.x + xv.y * w2.y + xv.z * w2.z + xv.w * w2.w;
            float s3 = xv.x * w3.x + xv.y * w3.y + xv.z * w3.z + xv.w * w3.w;
            float v = reduce4_heads(s0, s1, s2, s3, lane);
            if (lane < 4) sc_f[n * 4 + lane] = (v + b_l) * tinv;
        }
        seg_bar(seg);

        // ---- softmax stats: thread owns <=1 node (len <= 128) ----
        float4 sv = (st < len) ? sc_s[st]
                               : make_float4(-INFINITY, -INFINITY, -INFINITY, -INFINITY);
        float4 m = sv;
        #pragma unroll
        for (int off = 16; off > 0; off >>= 1) {
            m.x = fmaxf(m.x, __shfl_xor_sync(0xFFFFFFFFu, m.x, off));
            m.y = fmaxf(m.y, __shfl_xor_sync(0xFFFFFFFFu, m.y, off));
            m.z = fmaxf(m.z, __shfl_xor_sync(0xFFFFFFFFu, m.z, off));
            m.w = fmaxf(m.w, __shfl_xor_sync(0xFFFFFFFFu, m.w, off));
        }
        if (lane == 0) wred[wl] = m;
        seg_bar(seg);
        float4 M;
        {
            float4 a = wred[0], c = wred[1], e = wred[2], g = wred[3];
            M.x = fmaxf(fmaxf(a.x, c.x), fmaxf(e.x, g.x));
            M.y = fmaxf(fmaxf(a.y, c.y), fmaxf(e.y, g.y));
            M.z = fmaxf(fmaxf(a.z, c.z), fmaxf(e.z, g.z));
            M.w = fmaxf(fmaxf(a.w, c.w), fmaxf(e.w, g.w));
        }
        seg_bar(seg);

        float e0 = 0.f, e1 = 0.f, e2 = 0.f, e3 = 0.f;
        if (st < len) {
            e0 = __expf(sv.x - M.x); e1 = __expf(sv.y - M.y);
            e2 = __expf(sv.z - M.z); e3 = __expf(sv.w - M.w);
        }
        float4 s4 = make_float4(e0, e1, e2, e3);
        #pragma unroll
        for (int off = 16; off > 0; off >>= 1) {
            s4.x += __shfl_xor_sync(0xFFFFFFFFu, s4.x, off);
            s4.y += __shfl_xor_sync(0xFFFFFFFFu, s4.y, off);
            s4.z += __shfl_xor_sync(0xFFFFFFFFu, s4.z, off);
            s4.w += __shfl_xor_sync(0xFFFFFFFFu, s4.w, off);
        }
        if (lane == 0) wred[wl] = s4;
        seg_bar(seg);
        float4 R;
        {
            float4 a = wred[0], c = wred[1], e = wred[2], g = wred[3];
            float sx = a.x + c.x + e.x + g.x;
            float sy = a.y + c.y + e.y + g.y;
            float sz = a.z + c.z + e.z + g.z;
            float sw = a.w + c.w + e.w + g.w;
            R.x = (len > 0) ? 1.0f / sx : 0.f;
            R.y = (len > 0) ? 1.0f / sy : 0.f;
            R.z = (len > 0) ? 1.0f / sz : 0.f;
            R.w = (len > 0) ? 1.0f / sw : 0.f;
        }

        // ---- attn output + per-node mean weight ----
        if (st < len) {
            float a0 = e0 * R.x, a1 = e1 * R.y, a2 = e2 * R.z, a3 = e3 * R.w;
            size_t p = (size_t)start + st;
            out_attn[p]                 = a0;
            out_attn[(size_t)N + p]     = a1;
            out_attn[2 * (size_t)N + p] = a2;
            out_attn[3 * (size_t)N + p] = a3;
            w_s[st] = 0.25f * (a0 + a1 + a2 + a3);
        }
        seg_bar(seg);

        // ---- pooled: register rows free; tail rows re-read (L1-hit) ----
        float4 acc = make_float4(0.f, 0.f, 0.f, 0.f);
        #pragma unroll
        for (int k = 0; k < KREG; k++) {
            int n = wl + k * WPS;
            if (n < len) {
                float wj = w_s[n];
                acc.x += wj * xr[k].x; acc.y += wj * xr[k].y;
                acc.z += wj * xr[k].z; acc.w += wj * xr[k].w;
            }
        }
        for (int n = wl + KREG * WPS; n < len; n += WPS) {
            float wj = w_s[n];
            float4 v = xg4[n * 32 + lane];
            acc.x += wj * v.x; acc.y += wj * v.y;
            acc.z += wj * v.z; acc.w += wj * v.w;
        }
        pool4[wl * 32 + lane] = acc;
        seg_bar(seg);
        if (wl == 0) {
            float4 r = pool4[lane];
            #pragma unroll
            for (int p = 1; p < 4; p++) {
                float4 t = pool4[p * 32 + lane];
                r.x += t.x; r.y += t.y; r.z += t.z; r.w += t.w;
            }
            ((float4*)(out_pooled + (size_t)b * D))[lane] = r;
        }
        return;
    }

    // ======================= fallback (len > FAST_CAP) =======================
    for (int n = wl; n < len; n += WPS) {
        float4 xv = xg4[n * 32 + lane];
        float s0 = xv.x * w0.x + xv.y * w0.y + xv.z * w0.z + xv.w * w0.w;
        float s1 = xv.x * w1.x + xv.y * w1.y + xv.z * w1.z + xv.w * w1.w;
        float s2 = xv.x * w2.x + xv.y * w2.y + xv.z * w2.z + xv.w * w2.w;
        float s3 = xv.x * w3.x + xv.y * w3.y + xv.z * w3.z + xv.w * w3.w;
        float v = reduce4_heads(s0, s1, s2, s3, lane);
        if (lane < 4)
            ((float*)&g_scores[start + n])[lane] = (v + b_l) * tinv;
    }
    seg_bar(seg);

    float4 m = make_float4(-INFINITY, -INFINITY, -INFINITY, -INFINITY);
    for (int i = st; i < len; i += 128) {
        float4 s = g_scores[start + i];
        m.x = fmaxf(m.x, s.x); m.y = fmaxf(m.y, s.y);
        m.z = fmaxf(m.z, s.z); m.w = fmaxf(m.w, s.w);
    }
    #pragma unroll
    for (int off = 16; off > 0; off >>= 1) {
        m.x = fmaxf(m.x, __shfl_xor_sync(0xFFFFFFFFu, m.x, off));
        m.y = fmaxf(m.y, __shfl_xor_sync(0xFFFFFFFFu, m.y, off));
        m.z = fmaxf(m.z, __shfl_xor_sync(0xFFFFFFFFu, m.z, off));
        m.w = fmaxf(m.w, __shfl_xor_sync(0xFFFFFFFFu, m.w, off));
    }
    if (lane == 0) wred[wl] = m;
    seg_bar(seg);
    float4 M;
    {
        float4 a = wred[0], c = wred[1], e = wred[2], g = wred[3];
        M.x = fmaxf(fmaxf(a.x, c.x), fmaxf(e.x, g.x));
        M.y = fmaxf(fmaxf(a.y, c.y), fmaxf(e.y, g.y));
        M.z = fmaxf(fmaxf(a.z, c.z), fmaxf(e.z, g.z));
        M.w = fmaxf(fmaxf(a.w, c.w), fmaxf(e.w, g.w));
    }
    seg_bar(seg);

    float4 sum = make_float4(0.f, 0.f, 0.f, 0.f);
    for (int i = st; i < len; i += 128) {
        float4 s = g_scores[start + i];
        sum.x += __expf(s.x - M.x); sum.y += __expf(s.y - M.y);
        sum.z += __expf(s.z - M.z); sum.w += __expf(s.w - M.w);
    }
    #pragma unroll
    for (int off = 16; off > 0; off >>= 1) {
        sum.x += __shfl_xor_sync(0xFFFFFFFFu, sum.x, off);
        sum.y += __shfl_xor_sync(0xFFFFFFFFu, sum.y, off);
        sum.z += __shfl_xor_sync(0xFFFFFFFFu, sum.z, off);
        sum.w += __shfl_xor_sync(0xFFFFFFFFu, sum.w, off);
    }
    if (lane == 0) wred[wl] = sum;
    seg_bar(seg);
    float4 R;
    {
        float4 a = wred[0], c = wred[1], e = wred[2], g = wred[3];
        R.x = 1.0f / (a.x + c.x + e.x + g.x);
        R.y = 1.0f / (a.y + c.y + e.y + g.y);
        R.z = 1.0f / (a.z + c.z + e.z + g.z);
        R.w = 1.0f / (a.w + c.w + e.w + g.w);
    }

    float4 acc = make_float4(0.f, 0.f, 0.f, 0.f);
    for (int c = 0; c < len; c += 128) {
        int cl = min(128, len - c);
        seg_bar(seg);
        if (st < cl) {
            float4 s = g_scores[start + c + st];
            float a0 = __expf(s.x - M.x) * R.x;
            float a1 = __expf(s.y - M.y) * R.y;
            float a2 = __expf(s.z - M.z) * R.z;
            float a3 = __expf(s.w - M.w) * R.w;
            size_t p = (size_t)start + c + st;
            out_attn[p]                 = a0;
            out_attn[(size_t)N + p]     = a1;
            out_attn[2 * (size_t)N + p] = a2;
            out_attn[3 * (size_t)N + p] = a3;
            w_s[st] = 0.25f * (a0 + a1 + a2 + a3);
        }
        seg_bar(seg);
        for (int j = wl; j < cl; j += WPS) {
            float wj = w_s[j];
            float4 v = xg4[(c + j) * 32 + lane];
            acc.x += wj * v.x; acc.y += wj * v.y;
            acc.z += wj * v.z; acc.w += wj * v.w;
        }
    }
    seg_bar(seg);
    pool4[wl * 32 + lane] = acc;
    seg_bar(seg);
    if (wl == 0) {
        float4 r = pool4[lane];
        #pragma unroll
        for (int p = 1; p < 4; p++) {
            float4 t = pool4[p * 32 + lane];
            r.x += t.x; r.y += t.y; r.z += t.z; r.w += t.w;
        }
        ((float4*)(out_pooled + (size_t)b * D))[lane] = r;
    }
}

// ---------------------------------------------------------------------------
extern "C" void kernel_launch(void* const* d_in, const int* in_sizes, int n_in,
                              void* d_out, int out_size)
{
    const float* x    = (const float*)d_in[0];
    const void*  ids  = d_in[1];
    const float* W    = (const float*)d_in[2];
    const float* bias = (const float*)d_in[3];
    const float* temp = (const float*)d_in[4];

    int N = in_sizes[1];
    int B = (out_size - H * N) / D;
    if (B < 1) B = 1;
    if (B > BMAX) B = BMAX;

    float* out_pooled = (float*)d_out;                   // [B, D]
    float* out_attn   = (float*)d_out + (size_t)B * D;   // [H, N]

    const int SMEM = 2 * 1168 * 4;   // 9344 bytes

    k_bounds<<<(B + 256) / 256, 256>>>(ids, N, B);
    k_fused<<<(B + 1) / 2, NT, SMEM>>>(x, W, bias, temp, out_pooled, out_attn, N, B);
}

// round 10
// speedup vs baseline: 1.0566x; 1.0566x over previous
#include <cuda_runtime.h>
#include <math.h>

#define D 128
#define H 4
#define NMAX 500000
#define BMAX 8192
#define WCAP 128        // per-warp fast-path segment cap (mean 61, sigma 7.8)
#define NT 256          // 8 warps per block, 1 segment per warp

// Global scratch (fallback path only) + segment starts.
__device__ float4 g_scores[NMAX];
__device__ int    g_seg_start[BMAX + 1];

// ---------------------------------------------------------------------------
// Dtype-agnostic ids (reference claims int64 but JAX x64-off gives int32).
// ---------------------------------------------------------------------------
__device__ __forceinline__ bool ids_are_64bit(const int* ids32, int N) {
    int j = ((N - 1) & 1) ? (N - 1) : (N - 2);
    if (j < 0) j = 0;
    return ids32[j] == 0;
}
__device__ __forceinline__ int get_id_raw(const void* ids, bool is64, int n) {
    return is64 ? (int)((const long long*)ids)[n] : ((const int*)ids)[n];
}

__global__ void k_bounds(const void* __restrict__ ids, int N, int B) {
    int b = blockIdx.x * blockDim.x + threadIdx.x;
    if (b > B) return;
    bool is64 = ids_are_64bit((const int*)ids, N);
    int lo = 0, hi = N;
    while (lo < hi) {
        int mid = (lo + hi) >> 1;
        if (get_id_raw(ids, is64, mid) < b) lo = mid + 1; else hi = mid;
    }
    g_seg_start[b] = lo;
}

// ---------------------------------------------------------------------------
// 4-head warp reduction in 6 shuffles. Lane l ends with the full 32-lane sum
// of head (l & 3), replicated across each 4-lane group.
// ---------------------------------------------------------------------------
__device__ __forceinline__ float reduce4_heads(float s0, float s1, float s2,
                                               float s3, int lane) {
    const unsigned FULL = 0xFFFFFFFFu;
    float a01_send = (lane & 1) ? s0 : s1;
    float a01 = ((lane & 1) ? s1 : s0) + __shfl_xor_sync(FULL, a01_send, 1);
    float a23_send = (lane & 1) ? s2 : s3;
    float a23 = ((lane & 1) ? s3 : s2) + __shfl_xor_sync(FULL, a23_send, 1);
    float b_send = (lane & 2) ? a01 : a23;
    float v = ((lane & 2) ? a23 : a01) + __shfl_xor_sync(FULL, b_send, 2);
    v += __shfl_xor_sync(FULL, v, 4);
    v += __shfl_xor_sync(FULL, v, 8);
    v += __shfl_xor_sync(FULL, v, 16);
    return v;
}

// ---------------------------------------------------------------------------
// Fused kernel: ONE WARP per segment. No block barriers at all — each warp
// is fully independent; sync is 3x __syncwarp only.
// Per-warp smem slice: sc[WCAP*4] scores/exp + w_s[WCAP] weights = 640 floats.
// ---------------------------------------------------------------------------
__global__ void __launch_bounds__(NT, 4) k_fused(
    const float* __restrict__ x,
    const float* __restrict__ W,
    const float* __restrict__ bias,
    const float* __restrict__ temp,
    float* __restrict__ out_pooled,   // [B, D]
    float* __restrict__ out_attn,     // [H, N]
    int N, int B)
{
    extern __shared__ float sdyn[];

    int tid  = threadIdx.x;
    int lane = tid & 31;
    int wid  = tid >> 5;                       // warp in block
    int b    = blockIdx.x * (NT / 32) + wid;   // segment id
    if (b >= B) return;

    float*  sc_f = sdyn + wid * 640;           // WCAP*4 floats
    float4* sc_4 = (float4*)sc_f;
    float*  w_s  = sc_f + WCAP * 4;            // WCAP floats

    int start = g_seg_start[b];
    int end   = g_seg_start[b + 1];
    int len   = end - start;

    float4 w0 = ((const float4*)W)[lane];
    float4 w1 = ((const float4*)W)[32 + lane];
    float4 w2 = ((const float4*)W)[64 + lane];
    float4 w3 = ((const float4*)W)[96 + lane];
    float  b_l  = bias[lane & 3];
    float  tinv = 1.0f / temp[0];

    const float4* xg4 = (const float4*)(x + (size_t)start * D);
    const unsigned FULL = 0xFFFFFFFFu;

    if (len <= WCAP) {
        // ---- scores: warp streams its rows; unroll-4 batches the loads ----
        #pragma unroll 4
        for (int n = 0; n < len; n++) {
            float4 xv = xg4[n * 32 + lane];
            float s0 = xv.x * w0.x + xv.y * w0.y + xv.z * w0.z + xv.w * w0.w;
            float s1 = xv.x * w1.x + xv.y * w1.y + xv.z * w1.z + xv.w * w1.w;
            float s2 = xv.x * w2.x + xv.y * w2.y + xv.z * w2.z + xv.w * w2.w;
            float s3 = xv.x * w3.x + xv.y * w3.y + xv.z * w3.z + xv.w * w3.w;
            float v = reduce4_heads(s0, s1, s2, s3, lane);
            if (lane < 4) sc_f[n * 4 + lane] = (v + b_l) * tinv;
        }
        __syncwarp();

        // ---- max over segment (warp shuffles only) ----
        float4 m = make_float4(-INFINITY, -INFINITY, -INFINITY, -INFINITY);
        for (int i = lane; i < len; i += 32) {
            float4 s = sc_4[i];
            m.x = fmaxf(m.x, s.x); m.y = fmaxf(m.y, s.y);
            m.z = fmaxf(m.z, s.z); m.w = fmaxf(m.w, s.w);
        }
        #pragma unroll
        for (int off = 16; off > 0; off >>= 1) {
            m.x = fmaxf(m.x, __shfl_xor_sync(FULL, m.x, off));
            m.y = fmaxf(m.y, __shfl_xor_sync(FULL, m.y, off));
            m.z = fmaxf(m.z, __shfl_xor_sync(FULL, m.z, off));
            m.w = fmaxf(m.w, __shfl_xor_sync(FULL, m.w, off));
        }

        // ---- exp (stored in place) + sum ----
        float4 sum = make_float4(0.f, 0.f, 0.f, 0.f);
        for (int i = lane; i < len; i += 32) {
            float4 s = sc_4[i];
            float4 e;
            e.x = __expf(s.x - m.x); e.y = __expf(s.y - m.y);
            e.z = __expf(s.z - m.z); e.w = __expf(s.w - m.w);
            sc_4[i] = e;
            sum.x += e.x; sum.y += e.y; sum.z += e.z; sum.w += e.w;
        }
        #pragma unroll
        for (int off = 16; off > 0; off >>= 1) {
            sum.x += __shfl_xor_sync(FULL, sum.x, off);
            sum.y += __shfl_xor_sync(FULL, sum.y, off);
            sum.z += __shfl_xor_sync(FULL, sum.z, off);
            sum.w += __shfl_xor_sync(FULL, sum.w, off);
        }
        float4 R;
        R.x = 1.0f / sum.x; R.y = 1.0f / sum.y;
        R.z = 1.0f / sum.z; R.w = 1.0f / sum.w;
        __syncwarp();

        // ---- attn writes (coalesced per head) + per-node mean weight ----
        for (int i = lane; i < len; i += 32) {
            float4 e = sc_4[i];
            float a0 = e.x * R.x, a1 = e.y * R.y, a2 = e.z * R.z, a3 = e.w * R.w;
            size_t p = (size_t)start + i;
            out_attn[p]                 = a0;
            out_attn[(size_t)N + p]     = a1;
            out_attn[2 * (size_t)N + p] = a2;
            out_attn[3 * (size_t)N + p] = a3;
            w_s[i] = 0.25f * (a0 + a1 + a2 + a3);
        }
        __syncwarp();

        // ---- pooled: LDS-broadcast weight + L2-hot row re-read ----
        float4 acc = make_float4(0.f, 0.f, 0.f, 0.f);
        #pragma unroll 4
        for (int n = 0; n < len; n++) {
            float wj = w_s[n];
            float4 v = xg4[n * 32 + lane];
            acc.x += wj * v.x; acc.y += wj * v.y;
            acc.z += wj * v.z; acc.w += wj * v.w;
        }
        ((float4*)(out_pooled + (size_t)b * D))[lane] = acc;
        return;
    }

    // ============== fallback (len > WCAP): warp-only via g_scores ==========
    #pragma unroll 2
    for (int n = 0; n < len; n++) {
        float4 xv = xg4[n * 32 + lane];
        float s0 = xv.x * w0.x + xv.y * w0.y + xv.z * w0.z + xv.w * w0.w;
        float s1 = xv.x * w1.x + xv.y * w1.y + xv.z * w1.z + xv.w * w1.w;
        float s2 = xv.x * w2.x + xv.y * w2.y + xv.z * w2.z + xv.w * w2.w;
        float s3 = xv.x * w3.x + xv.y * w3.y + xv.z * w3.z + xv.w * w3.w;
        float v = reduce4_heads(s0, s1, s2, s3, lane);
        if (lane < 4)
            ((float*)&g_scores[start + n])[lane] = (v + b_l) * tinv;
    }
    __syncwarp();

    float4 m = make_float4(-INFINITY, -INFINITY, -INFINITY, -INFINITY);
    for (int i = lane; i < len; i += 32) {
        float4 s = g_scores[start + i];
        m.x = fmaxf(m.x, s.x); m.y = fmaxf(m.y, s.y);
        m.z = fmaxf(m.z, s.z); m.w = fmaxf(m.w, s.w);
    }
    #pragma unroll
    for (int off = 16; off > 0; off >>= 1) {
        m.x = fmaxf(m.x, __shfl_xor_sync(FULL, m.x, off));
        m.y = fmaxf(m.y, __shfl_xor_sync(FULL, m.y, off));
        m.z = fmaxf(m.z, __shfl_xor_sync(FULL, m.z, off));
        m.w = fmaxf(m.w, __shfl_xor_sync(FULL, m.w, off));
    }

    float4 sum = make_float4(0.f, 0.f, 0.f, 0.f);
    for (int i = lane; i < len; i += 32) {
        float4 s = g_scores[start + i];
        sum.x += __expf(s.x - m.x); sum.y += __expf(s.y - m.y);
        sum.z += __expf(s.z - m.z); sum.w += __expf(s.w - m.w);
    }
    #pragma unroll
    for (int off = 16; off > 0; off >>= 1) {
        sum.x += __shfl_xor_sync(FULL, sum.x, off);
        sum.y += __shfl_xor_sync(FULL, sum.y, off);
        sum.z += __shfl_xor_sync(FULL, sum.z, off);
        sum.w += __shfl_xor_sync(FULL, sum.w, off);
    }
    float4 R;
    R.x = 1.0f / sum.x; R.y = 1.0f / sum.y;
    R.z = 1.0f / sum.z; R.w = 1.0f / sum.w;

    // attn + overwrite g_scores[i].x with mean weight
    for (int i = lane; i < len; i += 32) {
        float4 s = g_scores[start + i];
        float a0 = __expf(s.x - m.x) * R.x;
        float a1 = __expf(s.y - m.y) * R.y;
        float a2 = __expf(s.z - m.z) * R.z;
        float a3 = __expf(s.w - m.w) * R.w;
        size_t p = (size_t)start + i;
        out_attn[p]                 = a0;
        out_attn[(size_t)N + p]     = a1;
        out_attn[2 * (size_t)N + p] = a2;
        out_attn[3 * (size_t)N + p] = a3;
        g_scores[start + i].x = 0.25f * (a0 + a1 + a2 + a3);
    }
    __syncwarp();

    float4 acc = make_float4(0.f, 0.f, 0.f, 0.f);
    #pragma unroll 2
    for (int n = 0; n < len; n++) {
        float wj = g_scores[start + n].x;
        float4 v = xg4[n * 32 + lane];
        acc.x += wj * v.x; acc.y += wj * v.y;
        acc.z += wj * v.z; acc.w += wj * v.w;
    }
    ((float4*)(out_pooled + (size_t)b * D))[lane] = acc;
}

// ---------------------------------------------------------------------------
extern "C" void kernel_launch(void* const* d_in, const int* in_sizes, int n_in,
                              void* d_out, int out_size)
{
    const float* x    = (const float*)d_in[0];
    const void*  ids  = d_in[1];
    const float* W    = (const float*)d_in[2];
    const float* bias = (const float*)d_in[3];
    const float* temp = (const float*)d_in[4];

    int N = in_sizes[1];
    int B = (out_size - H * N) / D;
    if (B < 1) B = 1;
    if (B > BMAX) B = BMAX;

    float* out_pooled = (float*)d_out;                   // [B, D]
    float* out_attn   = (float*)d_out + (size_t)B * D;   // [H, N]

    const int WARPS_PER_BLOCK = NT / 32;
    const int SMEM = WARPS_PER_BLOCK * 640 * 4;          // 20480 bytes

    k_bounds<<<(B + 256) / 256, 256>>>(ids, N, B);
    k_fused<<<(B + WARPS_PER_BLOCK - 1) / WARPS_PER_BLOCK, NT, SMEM>>>(
        x, W, bias, temp, out_pooled, out_attn, N, B);
}